// round 16
// baseline (speedup 1.0000x reference)
#include <cuda_runtime.h>
#include <cuda_fp16.h>
#include <cstdint>

// Problem constants
#define Bb   2
#define Ss   2048
#define Hh   1024
#define NHh  16
#define HDd  64
#define Mrows (Bb*Ss)   // 4096

// ---------------------------------------------------------------------------
// Device scratch (no allocations allowed). fp16 packed as half2 in uint32.
// ---------------------------------------------------------------------------
__device__ uint32_t g_xh[Mrows*Hh/2];        // X fp16
__device__ uint32_t g_wh[4*Hh*Hh/2];         // Wq,Wk,Wv,Wo fp16
__device__ uint32_t g_qh[Bb*NHh*Ss*HDd/2];   // Q fp16 (pre-scaled log2e/8), [b,h,s,d/2]
__device__ uint32_t g_kh[Bb*NHh*Ss*HDd/2];   // K fp16
__device__ uint32_t g_vh[Bb*NHh*Ss*HDd/2];   // V fp16
__device__ uint32_t g_ctxh[Bb*Ss*Hh/2];      // attention output fp16, [b,s,h]

__device__ __forceinline__ uint32_t packh2(float a, float b) {
    __half2 h = __floats2half2_rn(a, b);
    return *(uint32_t*)&h;
}

__device__ __forceinline__ void mma_f16(float d[4], const uint32_t a[4],
                                        const uint32_t b[2], const float c[4]) {
    asm volatile(
        "mma.sync.aligned.m16n8k16.row.col.f32.f16.f16.f32 "
        "{%0,%1,%2,%3}, {%4,%5,%6,%7}, {%8,%9}, {%10,%11,%12,%13};\n"
        : "=f"(d[0]), "=f"(d[1]), "=f"(d[2]), "=f"(d[3])
        : "r"(a[0]), "r"(a[1]), "r"(a[2]), "r"(a[3]),
          "r"(b[0]), "r"(b[1]),
          "f"(c[0]), "f"(c[1]), "f"(c[2]), "f"(c[3]));
}

__device__ __forceinline__ void cp_async16(uint32_t smem_addr, const void* gptr) {
    asm volatile("cp.async.cg.shared.global [%0], [%1], 16;\n"
                 :: "r"(smem_addr), "l"(gptr));
}
__device__ __forceinline__ uint32_t s2u(const void* p) {
    return (uint32_t)__cvta_generic_to_shared(p);
}

// ---------------------------------------------------------------------------
// Prologue: convert X and the 4 weight matrices to fp16 once (balanced 1D).
// ---------------------------------------------------------------------------
__global__ __launch_bounds__(256)
void preconv(const float* __restrict__ x,
             const float* __restrict__ wq, const float* __restrict__ wk,
             const float* __restrict__ wv, const float* __restrict__ wo)
{
    const int NX4 = (Mrows * Hh) / 4;   // 1,048,576
    const int NW4 = (Hh * Hh) / 4;      // 262,144
    const int i = blockIdx.x * blockDim.x + threadIdx.x;

    const float* src;
    uint32_t* dst;
    int j;
    if (i < NX4) {
        src = x; dst = g_xh; j = i;
    } else {
        const int w = i - NX4;
        const int z = w >> 18;
        j = w & (NW4 - 1);
        const float* ws[4] = {wq, wk, wv, wo};
        src = ws[z];
        dst = g_wh + (size_t)z * (Hh * Hh / 2);
    }
    float4 v = ((const float4*)src)[j];
    uint2 u;
    u.x = packh2(v.x, v.y);
    u.y = packh2(v.z, v.w);
    ((uint2*)dst)[j] = u;
}

// ---------------------------------------------------------------------------
// fp16 GEMM (m16n8k16), cp.async 2-stage, BK=64 halves, CTA tile 128x64.
// 128 threads, 4 warps (2m x 2n), warp tile 64x32 (mt=4, nt=4).
// Smaller tile -> 4 CTAs/SM residency, ~1 wave for gemm_out, denser mma issue.
// Stage: A 128x36 + B 64x36 u32 = 6912 words; 2 stages = 55296 bytes.
// dst: 0 -> Yout fp32; 1/2/3 -> g_qh/kh/vh fp16 (Q pre-scaled).
// ---------------------------------------------------------------------------
#define GEMM_ASTG  (128*36)
#define GEMM_STG   (128*36 + 64*36)           // u32 words per stage (A+B)
#define GEMM_SMEM  (2*GEMM_STG*4)             // 55296 bytes
#define LDAU       (Hh/2)

// Q pre-scale: (1/sqrt(64)) * log2(e) -> S matrix lands in log2 domain.
#define QSCALE_LOG2E 0.1803368801111f

__device__ __forceinline__
void gemm_load_stage(const uint32_t* __restrict__ A, const uint32_t* __restrict__ Bm,
                     uint32_t* dstA, int m0, int n0, int k0u, int tid)
{
    uint32_t* dstB = dstA + GEMM_ASTG;
    // A: 128 rows x 8 granules = 1024 granules (8 per thread)
#pragma unroll
    for (int j = 0; j < 8; j++) {
        const int id  = j * 128 + tid;
        const int row = id >> 3;
        const int col = (id & 7) * 4;
        cp_async16(s2u(dstA + row*36 + col), A + (size_t)(m0+row)*LDAU + k0u + col);
    }
    // B: 64 rows x 8 granules = 512 granules (4 per thread)
#pragma unroll
    for (int j = 0; j < 4; j++) {
        const int id  = j * 128 + tid;
        const int row = id >> 3;
        const int col = (id & 7) * 4;
        cp_async16(s2u(dstB + row*36 + col), Bm + (size_t)(n0+row)*LDAU + k0u + col);
    }
}

__device__ __forceinline__
void gemm_tc_body(const uint32_t* __restrict__ A, const uint32_t* __restrict__ Bm,
                  const float* __restrict__ bias, float* __restrict__ Yout,
                  int dst, int bx, int by, uint32_t* smem)
{
    const int tid  = threadIdx.x;
    const int lane = tid & 31;
    const int wid  = tid >> 5;
    const int wm   = (wid & 1) * 64;    // 2 warps along m
    const int wn   = (wid >> 1) * 32;   // 2 warps along n
    const int m0   = by * 128;
    const int n0   = bx * 64;
    const int g    = lane >> 2;
    const int tg   = lane & 3;

    float acc[4][4][4];
#pragma unroll
    for (int mt = 0; mt < 4; mt++)
#pragma unroll
        for (int nt = 0; nt < 4; nt++)
#pragma unroll
            for (int r = 0; r < 4; r++) acc[mt][nt][r] = 0.f;

    gemm_load_stage(A, Bm, smem, m0, n0, 0, tid);
    asm volatile("cp.async.commit_group;\n");

    for (int kt = 0; kt < 16; kt++) {
        if (kt + 1 < 16) {
            gemm_load_stage(A, Bm, smem + ((kt+1)&1)*GEMM_STG, m0, n0, (kt+1)*32, tid);
            asm volatile("cp.async.commit_group;\n");
            asm volatile("cp.async.wait_group 1;\n");
        } else {
            asm volatile("cp.async.wait_group 0;\n");
        }
        __syncthreads();

        const uint32_t* As = smem + (kt & 1) * GEMM_STG;
        const uint32_t* Bs = As + GEMM_ASTG;

#pragma unroll
        for (int kc8 = 0; kc8 < 32; kc8 += 8) {
            uint32_t af[4][4];
            uint32_t bf[4][2];
#pragma unroll
            for (int mt = 0; mt < 4; mt++) {
                const uint32_t* r0p = As + (wm + mt*16 + g)*36 + kc8;
                af[mt][0] = r0p[tg];
                af[mt][2] = r0p[tg + 4];
                const uint32_t* r1p = r0p + 8*36;
                af[mt][1] = r1p[tg];
                af[mt][3] = r1p[tg + 4];
            }
#pragma unroll
            for (int nt = 0; nt < 4; nt++) {
                const uint32_t* cp_ = Bs + (wn + nt*8 + g)*36 + kc8;
                bf[nt][0] = cp_[tg];
                bf[nt][1] = cp_[tg + 4];
            }
#pragma unroll
            for (int mt = 0; mt < 4; mt++)
#pragma unroll
                for (int nt = 0; nt < 4; nt++)
                    mma_f16(acc[mt][nt], af[mt], bf[nt], acc[mt][nt]);
        }
        __syncthreads();
    }

    const float qscale = (dst == 1) ? QSCALE_LOG2E : 1.0f;
#pragma unroll
    for (int mt = 0; mt < 4; mt++) {
#pragma unroll
        for (int nt = 0; nt < 4; nt++) {
            const int mA = m0 + wm + mt*16 + g;
            const int nA = n0 + wn + nt*8 + tg*2;
            const float b0 = bias[nA], b1 = bias[nA + 1];
#pragma unroll
            for (int half = 0; half < 2; half++) {
                const int m = mA + half * 8;
                float vx = acc[mt][nt][half*2 + 0] + b0;
                float vy = acc[mt][nt][half*2 + 1] + b1;
                if (dst == 0) {
                    float2 v; v.x = vx; v.y = vy;
                    *(float2*)&Yout[(size_t)m * Hh + nA] = v;
                } else {
                    const int bb   = m / Ss;
                    const int s    = m - bb * Ss;
                    const int head = nA >> 6;
                    const int d    = nA & 63;
                    uint32_t* dp = (dst == 1) ? g_qh : (dst == 2) ? g_kh : g_vh;
                    dp[(((size_t)(bb * NHh + head)) * Ss + s) * (HDd/2) + (d >> 1)] =
                        packh2(vx * qscale, vy * qscale);
                }
            }
        }
    }
}

__global__ __launch_bounds__(128)
void gemm_qkv(const float* __restrict__ bq, const float* __restrict__ bk,
              const float* __restrict__ bv)
{
    extern __shared__ uint32_t smem_g[];
    const int z = blockIdx.z;
    const float* bias = (z == 0) ? bq : (z == 1) ? bk : bv;
    gemm_tc_body(g_xh, g_wh + (size_t)z * (Hh * Hh / 2), bias, nullptr,
                 z + 1, blockIdx.x, blockIdx.y, smem_g);
}

__global__ __launch_bounds__(128)
void gemm_out(const float* __restrict__ bo, float* __restrict__ out)
{
    extern __shared__ uint32_t smem_g[];
    gemm_tc_body(g_ctxh, g_wh + (size_t)3 * (Hh * Hh / 2), bo, out,
                 0, blockIdx.x, blockIdx.y, smem_g);
}

// ---------------------------------------------------------------------------
// fp16 tensor-core causal flash attention (m16n8k16), round-15 winner
// verbatim (register-staged K/V pipeline, base-2 online softmax).
// grid: (S/64, B*NH), block 128 (4 warps, 16 q-rows each). Heavy tiles first.
// Static SMEM: 27648 bytes.
// ---------------------------------------------------------------------------
__global__ __launch_bounds__(128)
void attn_tc()
{
    __shared__ uint32_t Ksh[64][36];
    __shared__ uint32_t Vs2[32][72];
    __shared__ uint32_t Psh[64][36];

    const int tid  = threadIdx.x;
    const int lane = tid & 31;
    const int wid  = tid >> 5;
    const int g    = lane >> 2;
    const int tg   = lane & 3;
    const int qb   = gridDim.x - 1 - blockIdx.x;
    const int bh   = blockIdx.y;
    const int q0   = qb * 64;
    const int R0   = wid * 16;

    const uint32_t* Qg = g_qh + (size_t)bh * Ss * (HDd/2);
    const uint32_t* Kg = g_kh + (size_t)bh * Ss * (HDd/2);
    const uint32_t* Vg = g_vh + (size_t)bh * Ss * (HDd/2);

    int kr_[4], kc_[4], vkp_[4], vd4_[4];
#pragma unroll
    for (int j = 0; j < 4; j++) {
        const int id = j * 128 + tid;
        kr_[j]  = id >> 3;
        kc_[j]  = (id & 7) * 4;
        vkp_[j] = id >> 4;
        vd4_[j] = (id & 15) * 4;
    }

    for (int u = tid; u < 64 * 8; u += 128) {
        const int r = u >> 3;
        const int c = (u & 7) * 4;
        *(uint4*)&Ksh[r][c] = *(const uint4*)&Qg[(size_t)(q0 + r) * 32 + c];
    }
    __syncthreads();

    uint32_t qf[4][4];
#pragma unroll
    for (int c = 0; c < 4; c++) {
        qf[c][0] = Ksh[R0 + g][c * 8 + tg];
        qf[c][1] = Ksh[R0 + g + 8][c * 8 + tg];
        qf[c][2] = Ksh[R0 + g][c * 8 + tg + 4];
        qf[c][3] = Ksh[R0 + g + 8][c * 8 + tg + 4];
    }

    uint4 kreg[4];
    uint2 vra[4], vrb[4];
#pragma unroll
    for (int j = 0; j < 4; j++) {
        kreg[j] = *(const uint4*)&Kg[(size_t)kr_[j] * 32 + kc_[j]];
        vra[j]  = *(const uint2*)&Vg[(size_t)(2*vkp_[j])     * 32 + (vd4_[j] >> 1)];
        vrb[j]  = *(const uint2*)&Vg[(size_t)(2*vkp_[j] + 1) * 32 + (vd4_[j] >> 1)];
    }

    float oacc[8][4];
#pragma unroll
    for (int nt = 0; nt < 8; nt++)
#pragma unroll
        for (int r = 0; r < 4; r++) oacc[nt][r] = 0.f;
    float m0 = -1e30f, m1 = -1e30f, l0 = 0.f, l1 = 0.f;

    for (int kb = 0; kb <= qb; kb++) {
        __syncthreads();

#pragma unroll
        for (int j = 0; j < 4; j++) {
            *(uint4*)&Ksh[kr_[j]][kc_[j]] = kreg[j];
            uint4 o;
            o.x = (vra[j].x & 0xffffu) | (vrb[j].x << 16);
            o.y = (vra[j].x >> 16)     | (vrb[j].x & 0xffff0000u);
            o.z = (vra[j].y & 0xffffu) | (vrb[j].y << 16);
            o.w = (vra[j].y >> 16)     | (vrb[j].y & 0xffff0000u);
            *(uint4*)&Vs2[vkp_[j]][vd4_[j]] = o;
        }
        __syncthreads();

        if (kb < qb) {
            const int k0n = (kb + 1) * 64;
#pragma unroll
            for (int j = 0; j < 4; j++) {
                kreg[j] = *(const uint4*)&Kg[(size_t)(k0n + kr_[j]) * 32 + kc_[j]];
                vra[j]  = *(const uint2*)&Vg[(size_t)(k0n + 2*vkp_[j])     * 32 + (vd4_[j] >> 1)];
                vrb[j]  = *(const uint2*)&Vg[(size_t)(k0n + 2*vkp_[j] + 1) * 32 + (vd4_[j] >> 1)];
            }
        }

        float sacc[8][4];
#pragma unroll
        for (int nt = 0; nt < 8; nt++)
#pragma unroll
            for (int r = 0; r < 4; r++) sacc[nt][r] = 0.f;

#pragma unroll
        for (int c = 0; c < 4; c++) {
#pragma unroll
            for (int nt = 0; nt < 8; nt++) {
                uint32_t kf[2];
                kf[0] = Ksh[nt * 8 + g][c * 8 + tg];
                kf[1] = Ksh[nt * 8 + g][c * 8 + tg + 4];
                mma_f16(sacc[nt], qf[c], kf, sacc[nt]);
            }
        }

        if (kb == qb) {
            const int r0 = R0 + g;
            const int r1 = r0 + 8;
#pragma unroll
            for (int nt = 0; nt < 8; nt++) {
                const int c0 = nt * 8 + tg * 2;
                if (c0 > r0)     sacc[nt][0] = -1e30f;
                if (c0 + 1 > r0) sacc[nt][1] = -1e30f;
                if (c0 > r1)     sacc[nt][2] = -1e30f;
                if (c0 + 1 > r1) sacc[nt][3] = -1e30f;
            }
        }

        float bm0 = -1e30f, bm1 = -1e30f;
#pragma unroll
        for (int nt = 0; nt < 8; nt++) {
            bm0 = fmaxf(bm0, fmaxf(sacc[nt][0], sacc[nt][1]));
            bm1 = fmaxf(bm1, fmaxf(sacc[nt][2], sacc[nt][3]));
        }
        bm0 = fmaxf(bm0, __shfl_xor_sync(0xffffffffu, bm0, 1));
        bm0 = fmaxf(bm0, __shfl_xor_sync(0xffffffffu, bm0, 2));
        bm1 = fmaxf(bm1, __shfl_xor_sync(0xffffffffu, bm1, 1));
        bm1 = fmaxf(bm1, __shfl_xor_sync(0xffffffffu, bm1, 2));

        const float nm0 = fmaxf(m0, bm0);
        const float nm1 = fmaxf(m1, bm1);
        const float c0f = exp2f(m0 - nm0);
        const float c1f = exp2f(m1 - nm1);
        m0 = nm0; m1 = nm1;
#pragma unroll
        for (int nt = 0; nt < 8; nt++) {
            oacc[nt][0] *= c0f; oacc[nt][1] *= c0f;
            oacc[nt][2] *= c1f; oacc[nt][3] *= c1f;
        }
        l0 *= c0f; l1 *= c1f;

        float rs0 = 0.f, rs1 = 0.f;
#pragma unroll
        for (int nt = 0; nt < 8; nt++) {
            float p0 = exp2f(sacc[nt][0] - nm0);
            float p1 = exp2f(sacc[nt][1] - nm0);
            float p2 = exp2f(sacc[nt][2] - nm1);
            float p3 = exp2f(sacc[nt][3] - nm1);
            rs0 += p0 + p1;
            rs1 += p2 + p3;
            Psh[R0 + g][nt * 4 + tg]     = packh2(p0, p1);
            Psh[R0 + g + 8][nt * 4 + tg] = packh2(p2, p3);
        }
        rs0 += __shfl_xor_sync(0xffffffffu, rs0, 1);
        rs0 += __shfl_xor_sync(0xffffffffu, rs0, 2);
        rs1 += __shfl_xor_sync(0xffffffffu, rs1, 1);
        rs1 += __shfl_xor_sync(0xffffffffu, rs1, 2);
        l0 += rs0; l1 += rs1;

        __syncwarp();

#pragma unroll
        for (int c = 0; c < 4; c++) {
            uint32_t af[4];
            af[0] = Psh[R0 + g][c * 8 + tg];
            af[1] = Psh[R0 + g + 8][c * 8 + tg];
            af[2] = Psh[R0 + g][c * 8 + tg + 4];
            af[3] = Psh[R0 + g + 8][c * 8 + tg + 4];
#pragma unroll
            for (int nt = 0; nt < 8; nt++) {
                uint32_t bf[2];
                bf[0] = Vs2[c * 8 + tg][nt * 8 + g];
                bf[1] = Vs2[c * 8 + tg + 4][nt * 8 + g];
                mma_f16(oacc[nt], af, bf, oacc[nt]);
            }
        }
    }

    const float inv0 = 1.f / l0;
    const float inv1 = 1.f / l1;
    const int b    = bh / NHh;
    const int head = bh - b * NHh;
    const int s0   = q0 + R0 + g;
    const int s1   = s0 + 8;
#pragma unroll
    for (int nt = 0; nt < 8; nt++) {
        const int col = head * 64 + nt * 8 + tg * 2;
        g_ctxh[((size_t)(b * Ss) + s0) * (Hh/2) + (col >> 1)] =
            packh2(oacc[nt][0] * inv0, oacc[nt][1] * inv0);
        g_ctxh[((size_t)(b * Ss) + s1) * (Hh/2) + (col >> 1)] =
            packh2(oacc[nt][2] * inv1, oacc[nt][3] * inv1);
    }
}

// ---------------------------------------------------------------------------
// kernel_launch
// inputs: 0 hidden_states, 1 Wq, 2 bq, 3 Wk, 4 bk, 5 Wv, 6 bv, 7 Wo, 8 bo
// ---------------------------------------------------------------------------
extern "C" void kernel_launch(void* const* d_in, const int* in_sizes, int n_in,
                              void* d_out, int out_size)
{
    const float* x  = (const float*)d_in[0];
    const float* Wq = (const float*)d_in[1];
    const float* bq = (const float*)d_in[2];
    const float* Wk = (const float*)d_in[3];
    const float* bk = (const float*)d_in[4];
    const float* Wv = (const float*)d_in[5];
    const float* bv = (const float*)d_in[6];
    const float* Wo = (const float*)d_in[7];
    const float* bo = (const float*)d_in[8];
    float* out = (float*)d_out;

    cudaFuncSetAttribute(gemm_qkv, cudaFuncAttributeMaxDynamicSharedMemorySize, GEMM_SMEM);
    cudaFuncSetAttribute(gemm_out, cudaFuncAttributeMaxDynamicSharedMemorySize, GEMM_SMEM);

    preconv<<<8192, 256>>>(x, Wq, Wk, Wv, Wo);

    dim3 qkvgrid(Hh / 64, Mrows / 128, 3);    // (16, 32, 3) = 1536 CTAs
    gemm_qkv<<<qkvgrid, 128, GEMM_SMEM>>>(bq, bk, bv);

    dim3 agrid(Ss / 64, Bb * NHh);            // (32, 32)
    attn_tc<<<agrid, 128>>>();

    dim3 ogrid(Hh / 64, Mrows / 128);         // (16, 32) = 512 CTAs
    gemm_out<<<ogrid, 128, GEMM_SMEM>>>(bo, out);
}

// round 17
// speedup vs baseline: 1.0438x; 1.0438x over previous
#include <cuda_runtime.h>
#include <cuda_fp16.h>
#include <cstdint>

// Problem constants
#define Bb   2
#define Ss   2048
#define Hh   1024
#define NHh  16
#define HDd  64
#define Mrows (Bb*Ss)   // 4096

// ---------------------------------------------------------------------------
// Device scratch (no allocations allowed). fp16 packed as half2 in uint32.
// ---------------------------------------------------------------------------
__device__ uint32_t g_xh[Mrows*Hh/2];        // X fp16
__device__ uint32_t g_wh[4*Hh*Hh/2];         // Wq,Wk,Wv,Wo fp16
__device__ uint32_t g_qh[Bb*NHh*Ss*HDd/2];   // Q fp16 (pre-scaled log2e/8), [b,h,s,d/2]
__device__ uint32_t g_kh[Bb*NHh*Ss*HDd/2];   // K fp16
__device__ uint32_t g_vh[Bb*NHh*Ss*HDd/2];   // V fp16
__device__ uint32_t g_ctxh[Bb*Ss*Hh/2];      // attention output fp16, [b,s,h]

__device__ __forceinline__ uint32_t packh2(float a, float b) {
    __half2 h = __floats2half2_rn(a, b);
    return *(uint32_t*)&h;
}

__device__ __forceinline__ void mma_f16(float d[4], const uint32_t a[4],
                                        const uint32_t b[2], const float c[4]) {
    asm volatile(
        "mma.sync.aligned.m16n8k16.row.col.f32.f16.f16.f32 "
        "{%0,%1,%2,%3}, {%4,%5,%6,%7}, {%8,%9}, {%10,%11,%12,%13};\n"
        : "=f"(d[0]), "=f"(d[1]), "=f"(d[2]), "=f"(d[3])
        : "r"(a[0]), "r"(a[1]), "r"(a[2]), "r"(a[3]),
          "r"(b[0]), "r"(b[1]),
          "f"(c[0]), "f"(c[1]), "f"(c[2]), "f"(c[3]));
}

__device__ __forceinline__ void cp_async16(uint32_t smem_addr, const void* gptr) {
    asm volatile("cp.async.cg.shared.global [%0], [%1], 16;\n"
                 :: "r"(smem_addr), "l"(gptr));
}
__device__ __forceinline__ uint32_t s2u(const void* p) {
    return (uint32_t)__cvta_generic_to_shared(p);
}

// ---------------------------------------------------------------------------
// Prologue: convert X and the 4 weight matrices to fp16 once (balanced 1D).
// ---------------------------------------------------------------------------
__global__ __launch_bounds__(256)
void preconv(const float* __restrict__ x,
             const float* __restrict__ wq, const float* __restrict__ wk,
             const float* __restrict__ wv, const float* __restrict__ wo)
{
    const int NX4 = (Mrows * Hh) / 4;   // 1,048,576
    const int NW4 = (Hh * Hh) / 4;      // 262,144
    const int i = blockIdx.x * blockDim.x + threadIdx.x;

    const float* src;
    uint32_t* dst;
    int j;
    if (i < NX4) {
        src = x; dst = g_xh; j = i;
    } else {
        const int w = i - NX4;
        const int z = w >> 18;
        j = w & (NW4 - 1);
        const float* ws[4] = {wq, wk, wv, wo};
        src = ws[z];
        dst = g_wh + (size_t)z * (Hh * Hh / 2);
    }
    float4 v = ((const float4*)src)[j];
    uint2 u;
    u.x = packh2(v.x, v.y);
    u.y = packh2(v.z, v.w);
    ((uint2*)dst)[j] = u;
}

// ---------------------------------------------------------------------------
// fp16 GEMM (m16n8k16) with cp.async 2-stage pipeline, BK=64 — round-15
// winner, FROZEN: 128 threads, 4 warps (2m x 2n), warp tile 64x64, CTA 128x128.
// Dynamic SMEM: 2 stages x (A 128x36 + B 128x36) u32 = 73728 bytes.
// ---------------------------------------------------------------------------
#define GEMM_STG   (2*128*36)
#define GEMM_SMEM  (2*GEMM_STG*4)
#define LDAU       (Hh/2)

// Q pre-scale: (1/sqrt(64)) * log2(e) -> S matrix lands in log2 domain.
#define QSCALE_LOG2E 0.1803368801111f

__device__ __forceinline__
void gemm_load_stage(const uint32_t* __restrict__ A, const uint32_t* __restrict__ Bm,
                     uint32_t* dstA, int m0, int n0, int k0u, int tid)
{
    uint32_t* dstB = dstA + 128*36;
#pragma unroll
    for (int j = 0; j < 8; j++) {
        const int id  = j * 128 + tid;
        const int row = id >> 3;
        const int col = (id & 7) * 4;
        cp_async16(s2u(dstA + row*36 + col), A  + (size_t)(m0+row)*LDAU + k0u + col);
        cp_async16(s2u(dstB + row*36 + col), Bm + (size_t)(n0+row)*LDAU + k0u + col);
    }
}

__device__ __forceinline__
void gemm_tc_body(const uint32_t* __restrict__ A, const uint32_t* __restrict__ Bm,
                  const float* __restrict__ bias, float* __restrict__ Yout,
                  int dst, int bx, int by, uint32_t* smem)
{
    const int tid  = threadIdx.x;
    const int lane = tid & 31;
    const int wid  = tid >> 5;
    const int wm   = (wid & 1) * 64;
    const int wn   = (wid >> 1) * 64;
    const int m0   = by * 128;
    const int n0   = bx * 128;
    const int g    = lane >> 2;
    const int tg   = lane & 3;

    float acc[4][8][4];
#pragma unroll
    for (int mt = 0; mt < 4; mt++)
#pragma unroll
        for (int nt = 0; nt < 8; nt++)
#pragma unroll
            for (int r = 0; r < 4; r++) acc[mt][nt][r] = 0.f;

    gemm_load_stage(A, Bm, smem, m0, n0, 0, tid);
    asm volatile("cp.async.commit_group;\n");

    for (int kt = 0; kt < 16; kt++) {
        if (kt + 1 < 16) {
            gemm_load_stage(A, Bm, smem + ((kt+1)&1)*GEMM_STG, m0, n0, (kt+1)*32, tid);
            asm volatile("cp.async.commit_group;\n");
            asm volatile("cp.async.wait_group 1;\n");
        } else {
            asm volatile("cp.async.wait_group 0;\n");
        }
        __syncthreads();

        const uint32_t* As = smem + (kt & 1) * GEMM_STG;
        const uint32_t* Bs = As + 128*36;

#pragma unroll
        for (int kc8 = 0; kc8 < 32; kc8 += 8) {
            uint32_t af[4][4];
            uint32_t bf[8][2];
#pragma unroll
            for (int mt = 0; mt < 4; mt++) {
                const uint32_t* r0p = As + (wm + mt*16 + g)*36 + kc8;
                af[mt][0] = r0p[tg];
                af[mt][2] = r0p[tg + 4];
                const uint32_t* r1p = r0p + 8*36;
                af[mt][1] = r1p[tg];
                af[mt][3] = r1p[tg + 4];
            }
#pragma unroll
            for (int nt = 0; nt < 8; nt++) {
                const uint32_t* cp_ = Bs + (wn + nt*8 + g)*36 + kc8;
                bf[nt][0] = cp_[tg];
                bf[nt][1] = cp_[tg + 4];
            }
#pragma unroll
            for (int mt = 0; mt < 4; mt++)
#pragma unroll
                for (int nt = 0; nt < 8; nt++)
                    mma_f16(acc[mt][nt], af[mt], bf[nt], acc[mt][nt]);
        }
        __syncthreads();
    }

    const float qscale = (dst == 1) ? QSCALE_LOG2E : 1.0f;
#pragma unroll
    for (int mt = 0; mt < 4; mt++) {
#pragma unroll
        for (int nt = 0; nt < 8; nt++) {
            const int mA = m0 + wm + mt*16 + g;
            const int nA = n0 + wn + nt*8 + tg*2;
            const float b0 = bias[nA], b1 = bias[nA + 1];
#pragma unroll
            for (int half = 0; half < 2; half++) {
                const int m = mA + half * 8;
                float vx = acc[mt][nt][half*2 + 0] + b0;
                float vy = acc[mt][nt][half*2 + 1] + b1;
                if (dst == 0) {
                    float2 v; v.x = vx; v.y = vy;
                    *(float2*)&Yout[(size_t)m * Hh + nA] = v;
                } else {
                    const int bb   = m / Ss;
                    const int s    = m - bb * Ss;
                    const int head = nA >> 6;
                    const int d    = nA & 63;
                    uint32_t* dp = (dst == 1) ? g_qh : (dst == 2) ? g_kh : g_vh;
                    dp[(((size_t)(bb * NHh + head)) * Ss + s) * (HDd/2) + (d >> 1)] =
                        packh2(vx * qscale, vy * qscale);
                }
            }
        }
    }
}

__global__ __launch_bounds__(128)
void gemm_qkv(const float* __restrict__ bq, const float* __restrict__ bk,
              const float* __restrict__ bv)
{
    extern __shared__ uint32_t smem_g[];
    const int z = blockIdx.z;
    const float* bias = (z == 0) ? bq : (z == 1) ? bk : bv;
    gemm_tc_body(g_xh, g_wh + (size_t)z * (Hh * Hh / 2), bias, nullptr,
                 z + 1, blockIdx.x, blockIdx.y, smem_g);
}

__global__ __launch_bounds__(128)
void gemm_out(const float* __restrict__ bo, float* __restrict__ out)
{
    extern __shared__ uint32_t smem_g[];
    gemm_tc_body(g_ctxh, g_wh + (size_t)3 * (Hh * Hh / 2), bo, out,
                 0, blockIdx.x, blockIdx.y, smem_g);
}

// ---------------------------------------------------------------------------
// fp16 tensor-core causal flash attention (m16n8k16), v8:
// round-15 structure + double-buffered K/V SMEM -> ONE __syncthreads per
// k-tile (stores to buffer kb&1 cannot collide with reads of the same buffer,
// which ended at tile kb-2, strictly before tile kb-1's barrier).
// grid: (S/64, B*NH), block 128 (4 warps, 16 q-rows each). Heavy tiles first.
// Static SMEM: 2*9216 + 2*9216 + 9216 = 46080 bytes.
// ---------------------------------------------------------------------------
__global__ __launch_bounds__(128)
void attn_tc()
{
    __shared__ uint32_t Ksh[2][64][36];
    __shared__ uint32_t Vs2[2][32][72];
    __shared__ uint32_t Psh[64][36];

    const int tid  = threadIdx.x;
    const int lane = tid & 31;
    const int wid  = tid >> 5;
    const int g    = lane >> 2;
    const int tg   = lane & 3;
    const int qb   = gridDim.x - 1 - blockIdx.x;
    const int bh   = blockIdx.y;
    const int q0   = qb * 64;
    const int R0   = wid * 16;

    const uint32_t* Qg = g_qh + (size_t)bh * Ss * (HDd/2);
    const uint32_t* Kg = g_kh + (size_t)bh * Ss * (HDd/2);
    const uint32_t* Vg = g_vh + (size_t)bh * Ss * (HDd/2);

    int kr_[4], kc_[4], vkp_[4], vd4_[4];
#pragma unroll
    for (int j = 0; j < 4; j++) {
        const int id = j * 128 + tid;
        kr_[j]  = id >> 3;
        kc_[j]  = (id & 7) * 4;
        vkp_[j] = id >> 4;
        vd4_[j] = (id & 15) * 4;
    }

    // ---- stage Q (fp16 packed, pre-scaled) into Ksh[0], pull fragments ----
    for (int u = tid; u < 64 * 8; u += 128) {
        const int r = u >> 3;
        const int c = (u & 7) * 4;
        *(uint4*)&Ksh[0][r][c] = *(const uint4*)&Qg[(size_t)(q0 + r) * 32 + c];
    }
    __syncthreads();

    uint32_t qf[4][4];
#pragma unroll
    for (int c = 0; c < 4; c++) {
        qf[c][0] = Ksh[0][R0 + g][c * 8 + tg];
        qf[c][1] = Ksh[0][R0 + g + 8][c * 8 + tg];
        qf[c][2] = Ksh[0][R0 + g][c * 8 + tg + 4];
        qf[c][3] = Ksh[0][R0 + g + 8][c * 8 + tg + 4];
    }
    __syncthreads();   // all warps extracted Q frags before buffer 0 is reused

    uint4 kreg[4];
    uint2 vra[4], vrb[4];
#pragma unroll
    for (int j = 0; j < 4; j++) {
        kreg[j] = *(const uint4*)&Kg[(size_t)kr_[j] * 32 + kc_[j]];
        vra[j]  = *(const uint2*)&Vg[(size_t)(2*vkp_[j])     * 32 + (vd4_[j] >> 1)];
        vrb[j]  = *(const uint2*)&Vg[(size_t)(2*vkp_[j] + 1) * 32 + (vd4_[j] >> 1)];
    }

    float oacc[8][4];
#pragma unroll
    for (int nt = 0; nt < 8; nt++)
#pragma unroll
        for (int r = 0; r < 4; r++) oacc[nt][r] = 0.f;
    float m0 = -1e30f, m1 = -1e30f, l0 = 0.f, l1 = 0.f;

    for (int kb = 0; kb <= qb; kb++) {
        const int buf = kb & 1;

        // ---- store staged registers to SMEM buffer (K direct, V interleaved) ----
#pragma unroll
        for (int j = 0; j < 4; j++) {
            *(uint4*)&Ksh[buf][kr_[j]][kc_[j]] = kreg[j];
            uint4 o;
            o.x = (vra[j].x & 0xffffu) | (vrb[j].x << 16);
            o.y = (vra[j].x >> 16)     | (vrb[j].x & 0xffff0000u);
            o.z = (vra[j].y & 0xffffu) | (vrb[j].y << 16);
            o.w = (vra[j].y >> 16)     | (vrb[j].y & 0xffff0000u);
            *(uint4*)&Vs2[buf][vkp_[j]][vd4_[j]] = o;
        }
        __syncthreads();   // single barrier: buffer filled; prev tile compute done

        // ---- issue loads for next tile (overlaps with compute below) ----
        if (kb < qb) {
            const int k0n = (kb + 1) * 64;
#pragma unroll
            for (int j = 0; j < 4; j++) {
                kreg[j] = *(const uint4*)&Kg[(size_t)(k0n + kr_[j]) * 32 + kc_[j]];
                vra[j]  = *(const uint2*)&Vg[(size_t)(k0n + 2*vkp_[j])     * 32 + (vd4_[j] >> 1)];
                vrb[j]  = *(const uint2*)&Vg[(size_t)(k0n + 2*vkp_[j] + 1) * 32 + (vd4_[j] >> 1)];
            }
        }

        // ---- S2 = Q K^T in log2 domain (Q pre-scaled by log2e/8) ----
        float sacc[8][4];
#pragma unroll
        for (int nt = 0; nt < 8; nt++)
#pragma unroll
            for (int r = 0; r < 4; r++) sacc[nt][r] = 0.f;

#pragma unroll
        for (int c = 0; c < 4; c++) {
#pragma unroll
            for (int nt = 0; nt < 8; nt++) {
                uint32_t kf[2];
                kf[0] = Ksh[buf][nt * 8 + g][c * 8 + tg];
                kf[1] = Ksh[buf][nt * 8 + g][c * 8 + tg + 4];
                mma_f16(sacc[nt], qf[c], kf, sacc[nt]);
            }
        }

        if (kb == qb) {
            const int r0 = R0 + g;
            const int r1 = r0 + 8;
#pragma unroll
            for (int nt = 0; nt < 8; nt++) {
                const int c0 = nt * 8 + tg * 2;
                if (c0 > r0)     sacc[nt][0] = -1e30f;
                if (c0 + 1 > r0) sacc[nt][1] = -1e30f;
                if (c0 > r1)     sacc[nt][2] = -1e30f;
                if (c0 + 1 > r1) sacc[nt][3] = -1e30f;
            }
        }

        // ---- online softmax (base 2): row max ----
        float bm0 = -1e30f, bm1 = -1e30f;
#pragma unroll
        for (int nt = 0; nt < 8; nt++) {
            bm0 = fmaxf(bm0, fmaxf(sacc[nt][0], sacc[nt][1]));
            bm1 = fmaxf(bm1, fmaxf(sacc[nt][2], sacc[nt][3]));
        }
        bm0 = fmaxf(bm0, __shfl_xor_sync(0xffffffffu, bm0, 1));
        bm0 = fmaxf(bm0, __shfl_xor_sync(0xffffffffu, bm0, 2));
        bm1 = fmaxf(bm1, __shfl_xor_sync(0xffffffffu, bm1, 1));
        bm1 = fmaxf(bm1, __shfl_xor_sync(0xffffffffu, bm1, 2));

        const float nm0 = fmaxf(m0, bm0);
        const float nm1 = fmaxf(m1, bm1);
        const float c0f = exp2f(m0 - nm0);
        const float c1f = exp2f(m1 - nm1);
        m0 = nm0; m1 = nm1;
#pragma unroll
        for (int nt = 0; nt < 8; nt++) {
            oacc[nt][0] *= c0f; oacc[nt][1] *= c0f;
            oacc[nt][2] *= c1f; oacc[nt][3] *= c1f;
        }
        l0 *= c0f; l1 *= c1f;

        // ---- P = exp2(S2 - m) -> Psh fp16 packed (own warp stripe) ----
        float rs0 = 0.f, rs1 = 0.f;
#pragma unroll
        for (int nt = 0; nt < 8; nt++) {
            float p0 = exp2f(sacc[nt][0] - nm0);
            float p1 = exp2f(sacc[nt][1] - nm0);
            float p2 = exp2f(sacc[nt][2] - nm1);
            float p3 = exp2f(sacc[nt][3] - nm1);
            rs0 += p0 + p1;
            rs1 += p2 + p3;
            Psh[R0 + g][nt * 4 + tg]     = packh2(p0, p1);
            Psh[R0 + g + 8][nt * 4 + tg] = packh2(p2, p3);
        }
        rs0 += __shfl_xor_sync(0xffffffffu, rs0, 1);
        rs0 += __shfl_xor_sync(0xffffffffu, rs0, 2);
        rs1 += __shfl_xor_sync(0xffffffffu, rs1, 1);
        rs1 += __shfl_xor_sync(0xffffffffu, rs1, 2);
        l0 += rs0; l1 += rs1;

        __syncwarp();

        // ---- O += P @ V (fp16), 4 k16-chunks over 64 keys ----
#pragma unroll
        for (int c = 0; c < 4; c++) {
            uint32_t af[4];
            af[0] = Psh[R0 + g][c * 8 + tg];
            af[1] = Psh[R0 + g + 8][c * 8 + tg];
            af[2] = Psh[R0 + g][c * 8 + tg + 4];
            af[3] = Psh[R0 + g + 8][c * 8 + tg + 4];
#pragma unroll
            for (int nt = 0; nt < 8; nt++) {
                uint32_t bf[2];
                bf[0] = Vs2[buf][c * 8 + tg][nt * 8 + g];
                bf[1] = Vs2[buf][c * 8 + tg + 4][nt * 8 + g];
                mma_f16(oacc[nt], af, bf, oacc[nt]);
            }
        }
    }

    // ---- normalize + writeback ctx fp16 ----
    const float inv0 = 1.f / l0;
    const float inv1 = 1.f / l1;
    const int b    = bh / NHh;
    const int head = bh - b * NHh;
    const int s0   = q0 + R0 + g;
    const int s1   = s0 + 8;
#pragma unroll
    for (int nt = 0; nt < 8; nt++) {
        const int col = head * 64 + nt * 8 + tg * 2;
        g_ctxh[((size_t)(b * Ss) + s0) * (Hh/2) + (col >> 1)] =
            packh2(oacc[nt][0] * inv0, oacc[nt][1] * inv0);
        g_ctxh[((size_t)(b * Ss) + s1) * (Hh/2) + (col >> 1)] =
            packh2(oacc[nt][2] * inv1, oacc[nt][3] * inv1);
    }
}

// ---------------------------------------------------------------------------
// kernel_launch
// inputs: 0 hidden_states, 1 Wq, 2 bq, 3 Wk, 4 bk, 5 Wv, 6 bv, 7 Wo, 8 bo
// ---------------------------------------------------------------------------
extern "C" void kernel_launch(void* const* d_in, const int* in_sizes, int n_in,
                              void* d_out, int out_size)
{
    const float* x  = (const float*)d_in[0];
    const float* Wq = (const float*)d_in[1];
    const float* bq = (const float*)d_in[2];
    const float* Wk = (const float*)d_in[3];
    const float* bk = (const float*)d_in[4];
    const float* Wv = (const float*)d_in[5];
    const float* bv = (const float*)d_in[6];
    const float* Wo = (const float*)d_in[7];
    const float* bo = (const float*)d_in[8];
    float* out = (float*)d_out;

    cudaFuncSetAttribute(gemm_qkv, cudaFuncAttributeMaxDynamicSharedMemorySize, GEMM_SMEM);
    cudaFuncSetAttribute(gemm_out, cudaFuncAttributeMaxDynamicSharedMemorySize, GEMM_SMEM);

    preconv<<<8192, 256>>>(x, Wq, Wk, Wv, Wo);

    dim3 qkvgrid(Hh / 128, Mrows / 128, 3);   // (8, 32, 3)
    gemm_qkv<<<qkvgrid, 128, GEMM_SMEM>>>(bq, bk, bv);

    dim3 agrid(Ss / 64, Bb * NHh);            // (32, 32)
    attn_tc<<<agrid, 128>>>();

    dim3 ogrid(Hh / 128, Mrows / 128);        // (8, 32)
    gemm_out<<<ogrid, 128, GEMM_SMEM>>>(bo, out);
}